// round 2
// baseline (speedup 1.0000x reference)
#include <cuda_runtime.h>

// ---------------- scratch buffers (device globals: no allocation allowed) ----
__device__ float g_h1[128*32*64*64];   // encoder conv1 out  [128,32,64,64]
__device__ float g_h2[128*64*32*32];   // encoder conv2 out  [128,64,32,32]
__device__ float g_z [128*64*32*32];   // encoder conv3 out  (z)
__device__ float g_zq[128*64*32*32];   // straight-through z_q
__device__ float g_d1[128*64*32*32];   // decoder deconv1 out
__device__ float g_d2[128*32*64*64];   // decoder deconv2 out
__device__ int   g_idx[128*32*32];     // argmin indices per pixel
__device__ float g_vq_part[32768];
__device__ float g_rec_part[512];

// =================== conv1: 1->32, 4x4, s2, p1, relu =========================
// in [128,1,128,128] -> out [128,32,64,64]
// grid (4 spatial, 2 co-group, 128 n), block 256; thread: 4 px * 16 co
__global__ void __launch_bounds__(256) k_conv1(const float* __restrict__ x,
                                               const float* __restrict__ w1,
                                               const float* __restrict__ b1) {
    __shared__ float ws[256];
    const int tid = threadIdx.x;
    const int s = blockIdx.x, cog = blockIdx.y, n = blockIdx.z;
    ws[tid] = w1[cog*256 + tid];       // w1[(cog*16+j)*16 + t]
    __syncthreads();
    const int y  = s*16 + (tid >> 4);
    const int x0 = (tid & 15) * 4;
    const float* xn = x + n*16384;
    float acc[16][4];
    #pragma unroll
    for (int j = 0; j < 16; j++) {
        float bv = b1[cog*16 + j];
        #pragma unroll
        for (int p = 0; p < 4; p++) acc[j][p] = bv;
    }
    #pragma unroll
    for (int ky = 0; ky < 4; ky++) {
        int iy = 2*y - 1 + ky;
        bool rok = (iy >= 0) && (iy < 128);
        float xv[10];
        #pragma unroll
        for (int c = 0; c < 10; c++) {
            int ix = 2*x0 - 1 + c;
            xv[c] = (rok && ix >= 0 && ix < 128) ? xn[iy*128 + ix] : 0.f;
        }
        #pragma unroll
        for (int j = 0; j < 16; j++) {
            #pragma unroll
            for (int kx = 0; kx < 4; kx++) {
                float w = ws[j*16 + ky*4 + kx];
                #pragma unroll
                for (int p = 0; p < 4; p++)
                    acc[j][p] = fmaf(xv[2*p + kx], w, acc[j][p]);
            }
        }
    }
    #pragma unroll
    for (int j = 0; j < 16; j++) {
        float4 o;
        o.x = fmaxf(acc[j][0], 0.f); o.y = fmaxf(acc[j][1], 0.f);
        o.z = fmaxf(acc[j][2], 0.f); o.w = fmaxf(acc[j][3], 0.f);
        *(float4*)&g_h1[(n*32 + cog*16 + j)*4096 + y*64 + x0] = o;
    }
}

// =================== conv2: 32->64, 4x4, s2, p1, relu ========================
// in [128,32,64,64] -> out [128,64,32,32]
// grid (4 co-group, 128 n), block 256; thread: 4 px * 16 co; full 32x32 plane
__global__ void __launch_bounds__(256) k_conv2(const float* __restrict__ w2,
                                               const float* __restrict__ b2) {
    __shared__ float ws[32*256];   // [ci][j][tap]
    const int tid = threadIdx.x;
    const int cog = blockIdx.x, n = blockIdx.y;
    for (int i = tid; i < 8192; i += 256) {
        int ci = i >> 8, r = i & 255, j = r >> 4, t = r & 15;
        ws[i] = w2[(cog*16 + j)*512 + ci*16 + t];   // w2[co][ci][4][4]
    }
    __syncthreads();
    const int y  = tid >> 3;
    const int x0 = (tid & 7) * 4;
    float acc[16][4];
    #pragma unroll
    for (int j = 0; j < 16; j++) {
        float bv = b2[cog*16 + j];
        #pragma unroll
        for (int p = 0; p < 4; p++) acc[j][p] = bv;
    }
    const float* inp = g_h1 + n*131072;
    for (int ci = 0; ci < 32; ci++) {
        const float* ic = inp + ci*4096;
        const float* wc = ws + ci*256;
        #pragma unroll
        for (int ky = 0; ky < 4; ky++) {
            int iy = 2*y - 1 + ky;
            bool rok = (iy >= 0) && (iy < 64);
            float xv[10];
            #pragma unroll
            for (int c = 0; c < 10; c++) {
                int ix = 2*x0 - 1 + c;
                xv[c] = (rok && ix >= 0 && ix < 64) ? ic[iy*64 + ix] : 0.f;
            }
            #pragma unroll
            for (int j = 0; j < 16; j++) {
                #pragma unroll
                for (int kx = 0; kx < 4; kx++) {
                    float w = wc[j*16 + ky*4 + kx];
                    #pragma unroll
                    for (int p = 0; p < 4; p++)
                        acc[j][p] = fmaf(xv[2*p + kx], w, acc[j][p]);
                }
            }
        }
    }
    #pragma unroll
    for (int j = 0; j < 16; j++) {
        float4 o;
        o.x = fmaxf(acc[j][0], 0.f); o.y = fmaxf(acc[j][1], 0.f);
        o.z = fmaxf(acc[j][2], 0.f); o.w = fmaxf(acc[j][3], 0.f);
        *(float4*)&g_h2[(n*64 + cog*16 + j)*1024 + y*32 + x0] = o;
    }
}

// ============ generic 64->64 3x3 s1 p1 conv on 32x32 (conv3 / deconv1) ======
// transposed=0: w[co][ci][3][3] direct.  transposed=1: torch ConvTranspose
// weights w[ci][co][3][3], spatially flipped (index 8-t).
__global__ void __launch_bounds__(256) k_conv3x3(const float* __restrict__ in,
                                                 const float* __restrict__ w,
                                                 const float* __restrict__ b,
                                                 float* __restrict__ out,
                                                 int transposed, int do_relu) {
    __shared__ float ws[64*144];   // [ci][j][tap]
    const int tid = threadIdx.x;
    const int cog = blockIdx.x, n = blockIdx.y;
    for (int i = tid; i < 9216; i += 256) {
        int ci = i / 144, r = i % 144, j = r / 9, t = r % 9;
        int co = cog*16 + j;
        ws[i] = transposed ? w[ci*576 + co*9 + (8 - t)]
                           : w[co*576 + ci*9 + t];
    }
    __syncthreads();
    const int y  = tid >> 3;
    const int x0 = (tid & 7) * 4;
    float acc[16][4];
    #pragma unroll
    for (int j = 0; j < 16; j++) {
        float bv = b[cog*16 + j];
        #pragma unroll
        for (int p = 0; p < 4; p++) acc[j][p] = bv;
    }
    const float* inp = in + n*65536;
    for (int ci = 0; ci < 64; ci++) {
        const float* ic = inp + ci*1024;
        const float* wc = ws + ci*144;
        #pragma unroll
        for (int ky = 0; ky < 3; ky++) {
            int iy = y - 1 + ky;
            bool rok = (iy >= 0) && (iy < 32);
            float xv[6];
            #pragma unroll
            for (int c = 0; c < 6; c++) {
                int ix = x0 - 1 + c;
                xv[c] = (rok && ix >= 0 && ix < 32) ? ic[iy*32 + ix] : 0.f;
            }
            #pragma unroll
            for (int j = 0; j < 16; j++) {
                #pragma unroll
                for (int kx = 0; kx < 3; kx++) {
                    float wv = wc[j*9 + ky*3 + kx];
                    #pragma unroll
                    for (int p = 0; p < 4; p++)
                        acc[j][p] = fmaf(xv[p + kx], wv, acc[j][p]);
                }
            }
        }
    }
    #pragma unroll
    for (int j = 0; j < 16; j++) {
        float4 o;
        if (do_relu) {
            o.x = fmaxf(acc[j][0], 0.f); o.y = fmaxf(acc[j][1], 0.f);
            o.z = fmaxf(acc[j][2], 0.f); o.w = fmaxf(acc[j][3], 0.f);
        } else {
            o.x = acc[j][0]; o.y = acc[j][1]; o.z = acc[j][2]; o.w = acc[j][3];
        }
        *(float4*)&out[(n*64 + cog*16 + j)*1024 + y*32 + x0] = o;
    }
}

// =================== VQ argmin: 131072 px, 128 codes, D=64 ===================
// grid 4096, block 256. Block handles 32 pixels vs all 128 codes.
// thread = (pg = tid>>5 pixel group of 4, cg = tid&31); codes {cg,32+cg,64+cg,96+cg}
__global__ void __launch_bounds__(256) k_quant(const float* __restrict__ cb) {
    __shared__ float4 zs4[64*8];        // [k][px/4] transposed z tile
    __shared__ float  cbs[64*129];      // [k][e] padded (conflict-free staging)
    const int tid = threadIdx.x;
    const int px0 = blockIdx.x * 32;
    const int n = px0 >> 10, hw0 = px0 & 1023;
    const float* zb = g_z + n*65536 + hw0;
    float* zsf = (float*)zs4;
    for (int i = tid; i < 2048; i += 256) {          // zs[k*32+px] = z[k][px]
        int k = i >> 5, px = i & 31;
        zsf[i] = zb[k*1024 + px];
    }
    for (int i = tid; i < 8192; i += 256) {          // cbs[k*129+e] = cb[e][k]
        int e = i >> 6, k = i & 63;
        cbs[k*129 + e] = cb[i];
    }
    __syncthreads();
    const int cg = tid & 31, pg = tid >> 5;
    float dot[4][4];
    float cc[4];
    #pragma unroll
    for (int j = 0; j < 4; j++) {
        cc[j] = 0.f;
        #pragma unroll
        for (int p = 0; p < 4; p++) dot[j][p] = 0.f;
    }
    for (int k = 0; k < 64; k++) {
        float4 zv = zs4[k*8 + pg];
        #pragma unroll
        for (int j = 0; j < 4; j++) {
            float c = cbs[k*129 + j*32 + cg];
            cc[j] = fmaf(c, c, cc[j]);
            dot[j][0] = fmaf(c, zv.x, dot[j][0]);
            dot[j][1] = fmaf(c, zv.y, dot[j][1]);
            dot[j][2] = fmaf(c, zv.z, dot[j][2]);
            dot[j][3] = fmaf(c, zv.w, dot[j][3]);
        }
    }
    #pragma unroll
    for (int p = 0; p < 4; p++) {
        float bv = cc[0] - 2.f*dot[0][p];
        int   be = cg;                              // e = 0*32+cg
        #pragma unroll
        for (int j = 1; j < 4; j++) {
            float v = cc[j] - 2.f*dot[j][p];
            int   e = j*32 + cg;
            if (v < bv || (v == bv && e < be)) { bv = v; be = e; }
        }
        #pragma unroll
        for (int off = 16; off; off >>= 1) {
            float ov = __shfl_down_sync(0xffffffffu, bv, off);
            int   oe = __shfl_down_sync(0xffffffffu, be, off);
            if (ov < bv || (ov == bv && oe < be)) { bv = ov; be = oe; }
        }
        if (cg == 0) g_idx[px0 + pg*4 + p] = be;
    }
}

// ============== gather z_q + straight-through + vq-loss partials =============
__global__ void __launch_bounds__(256) k_gather(const float* __restrict__ cb) {
    const int i = blockIdx.x*256 + threadIdx.x;      // over 8388608
    const int hw = i & 1023;
    const int nc = i >> 10;
    const int c = nc & 63, n = nc >> 6;
    int e = g_idx[n*1024 + hw];                      // batched early: warp issues
    float zi = g_z[i];                               // 32 gathers before use
    float v  = __ldg(&cb[e*64 + c]);
    g_zq[i] = zi + (v - zi);       // straight-through (bit-matches reference)
    float d = zi - v;
    float sq = d * d;
    #pragma unroll
    for (int off = 16; off; off >>= 1) sq += __shfl_down_sync(0xffffffffu, sq, off);
    __shared__ float red[8];
    int lane = threadIdx.x & 31, wid = threadIdx.x >> 5;
    if (lane == 0) red[wid] = sq;
    __syncthreads();
    if (threadIdx.x == 0) {
        float s = 0.f;
        #pragma unroll
        for (int w = 0; w < 8; w++) s += red[w];
        g_vq_part[blockIdx.x] = s;
    }
}

// ===== deconv2: ConvTranspose 64->32, 4x4, s2, p1, relu (gather form) ========
// in [128,64,32,32] -> out [128,32,64,64]
// grid (2 spatial, 4 o-group, 128 n), block 256; thread: 8 px * 8 o
__global__ void __launch_bounds__(256) k_deconv2(const float* __restrict__ dw2,
                                                 const float* __restrict__ db2) {
    __shared__ float ws[64*128];   // [ci][j][tap]
    const int tid = threadIdx.x;
    const int s = blockIdx.x, og = blockIdx.y, n = blockIdx.z;
    for (int i = tid; i < 8192; i += 256) {
        int ci = i >> 7, r = i & 127, j = r >> 4, t = r & 15;
        ws[i] = dw2[ci*512 + (og*8 + j)*16 + t];     // dw2[ci][o][4][4]
    }
    __syncthreads();
    const int y  = s*32 + (tid >> 3);
    const int x0 = (tid & 7) * 8;
    float acc[8][8];
    #pragma unroll
    for (int j = 0; j < 8; j++) {
        float bv = db2[og*8 + j];
        #pragma unroll
        for (int p = 0; p < 8; p++) acc[j][p] = bv;
    }
    const int pr  = (y + 1) & 1;                 // valid ky parity
    const int iy1 = (y + 1 - pr) >> 1;           // tap for ky = pr
    const int iy2 = iy1 - 1;                     // tap for ky = pr+2
    const bool r1ok = (iy1 >= 0) && (iy1 < 32);
    const bool r2ok = (iy2 >= 0) && (iy2 < 32);
    const int ixmin = (x0 - 2) >> 1;
    const float* inp = g_d1 + n*65536;
    for (int ci = 0; ci < 64; ci++) {
        const float* ic = inp + ci*1024;
        const float* wc = ws + ci*128;
        float xv0[6], xv1[6];
        #pragma unroll
        for (int c = 0; c < 6; c++) {
            int ix = ixmin + c;
            bool cok = (ix >= 0) && (ix < 32);
            xv0[c] = (r1ok && cok) ? ic[iy1*32 + ix] : 0.f;
            xv1[c] = (r2ok && cok) ? ic[iy2*32 + ix] : 0.f;
        }
        #pragma unroll
        for (int j = 0; j < 8; j++) {
            float w10 = wc[j*16 + pr*4 + 0];      // ky=pr row
            float w11 = wc[j*16 + pr*4 + 1];
            float w12 = wc[j*16 + pr*4 + 2];
            float w13 = wc[j*16 + pr*4 + 3];
            float w20 = wc[j*16 + (pr+2)*4 + 0];  // ky=pr+2 row
            float w21 = wc[j*16 + (pr+2)*4 + 1];
            float w22 = wc[j*16 + (pr+2)*4 + 2];
            float w23 = wc[j*16 + (pr+2)*4 + 3];
            #pragma unroll
            for (int p = 0; p < 8; p++) {
                const int kxa = (p + 1) & 1;            // valid kx parity
                const int ca  = ((p + 1) >> 1) + 1;     // col for kx=kxa
                float wa1 = kxa ? w11 : w10;
                float wb1 = kxa ? w13 : w12;            // kx = kxa+2
                float wa2 = kxa ? w21 : w20;
                float wb2 = kxa ? w23 : w22;
                float a = acc[j][p];
                a = fmaf(xv0[ca],   wa1, a);
                a = fmaf(xv0[ca-1], wb1, a);
                a = fmaf(xv1[ca],   wa2, a);
                a = fmaf(xv1[ca-1], wb2, a);
                acc[j][p] = a;
            }
        }
    }
    #pragma unroll
    for (int j = 0; j < 8; j++) {
        float* op = &g_d2[(n*32 + og*8 + j)*4096 + y*64 + x0];
        float4 o0, o1;
        o0.x = fmaxf(acc[j][0],0.f); o0.y = fmaxf(acc[j][1],0.f);
        o0.z = fmaxf(acc[j][2],0.f); o0.w = fmaxf(acc[j][3],0.f);
        o1.x = fmaxf(acc[j][4],0.f); o1.y = fmaxf(acc[j][5],0.f);
        o1.z = fmaxf(acc[j][6],0.f); o1.w = fmaxf(acc[j][7],0.f);
        *(float4*)op = o0;
        *(float4*)(op + 4) = o1;
    }
}

// ===== deconv3: ConvTranspose 32->1, 4x4, s2, p1, sigmoid + recon loss =======
// in [128,32,64,64] -> out [128,1,128,128]
// grid (4 spatial, 128 n), block 256; thread: 16 px
__global__ void __launch_bounds__(256) k_deconv3(const float* __restrict__ x,
                                                 const float* __restrict__ dw3,
                                                 const float* __restrict__ db3,
                                                 float* __restrict__ out) {
    __shared__ float ws[512];      // all weights dw3[32][1][4][4]
    const int tid = threadIdx.x;
    const int s = blockIdx.x, n = blockIdx.y;
    for (int i = tid; i < 512; i += 256) ws[i] = dw3[i];
    __syncthreads();
    const int y  = s*32 + (tid >> 3);
    const int x0 = (tid & 7) * 16;
    float acc[16];
    {
        float bv = db3[0];
        #pragma unroll
        for (int p = 0; p < 16; p++) acc[p] = bv;
    }
    const int pr  = (y + 1) & 1;
    const int iy1 = (y + 1 - pr) >> 1;
    const int iy2 = iy1 - 1;
    const bool r1ok = (iy1 >= 0) && (iy1 < 64);
    const bool r2ok = (iy2 >= 0) && (iy2 < 64);
    const int ixmin = (x0 - 2) >> 1;
    const float* inp = g_d2 + n*131072;
    for (int ci = 0; ci < 32; ci++) {
        const float* ic = inp + ci*4096;
        const float* wc = ws + ci*16;
        float xv0[10], xv1[10];
        #pragma unroll
        for (int c = 0; c < 10; c++) {
            int ix = ixmin + c;
            bool cok = (ix >= 0) && (ix < 64);
            xv0[c] = (r1ok && cok) ? ic[iy1*64 + ix] : 0.f;
            xv1[c] = (r2ok && cok) ? ic[iy2*64 + ix] : 0.f;
        }
        float w10 = wc[pr*4 + 0], w11 = wc[pr*4 + 1];
        float w12 = wc[pr*4 + 2], w13 = wc[pr*4 + 3];
        float w20 = wc[(pr+2)*4 + 0], w21 = wc[(pr+2)*4 + 1];
        float w22 = wc[(pr+2)*4 + 2], w23 = wc[(pr+2)*4 + 3];
        #pragma unroll
        for (int p = 0; p < 16; p++) {
            const int kxa = (p + 1) & 1;
            const int ca  = ((p + 1) >> 1) + 1;
            float wa1 = kxa ? w11 : w10;
            float wb1 = kxa ? w13 : w12;
            float wa2 = kxa ? w21 : w20;
            float wb2 = kxa ? w23 : w22;
            float a = acc[p];
            a = fmaf(xv0[ca],   wa1, a);
            a = fmaf(xv0[ca-1], wb1, a);
            a = fmaf(xv1[ca],   wa2, a);
            a = fmaf(xv1[ca-1], wb2, a);
            acc[p] = a;
        }
    }
    // sigmoid, write, accumulate recon-loss partial
    float ssum = 0.f;
    const int obase = n*16384 + y*128 + x0;
    #pragma unroll
    for (int p = 0; p < 16; p++) {
        float v = 1.f / (1.f + __expf(-acc[p]));
        out[obase + p] = v;
        float d = v - x[obase + p];
        ssum = fmaf(d, d, ssum);
    }
    #pragma unroll
    for (int off = 16; off; off >>= 1) ssum += __shfl_down_sync(0xffffffffu, ssum, off);
    __shared__ float red[8];
    int lane = tid & 31, wid = tid >> 5;
    if (lane == 0) red[wid] = ssum;
    __syncthreads();
    if (tid == 0) {
        float sacc = 0.f;
        #pragma unroll
        for (int w = 0; w < 8; w++) sacc += red[w];
        g_rec_part[n*4 + s] = sacc;
    }
}

// =================== final: reduce loss partials -> 2 scalars ================
__global__ void __launch_bounds__(256) k_final(float* __restrict__ out) {
    const int tid = threadIdx.x;
    float vs = 0.f, rs = 0.f;
    for (int i = tid; i < 32768; i += 256) vs += g_vq_part[i];
    for (int i = tid; i < 512;   i += 256) rs += g_rec_part[i];
    #pragma unroll
    for (int off = 16; off; off >>= 1) {
        vs += __shfl_down_sync(0xffffffffu, vs, off);
        rs += __shfl_down_sync(0xffffffffu, rs, off);
    }
    __shared__ float rv[8], rr[8];
    int lane = tid & 31, wid = tid >> 5;
    if (lane == 0) { rv[wid] = vs; rr[wid] = rs; }
    __syncthreads();
    if (tid == 0) {
        float v = 0.f, r = 0.f;
        #pragma unroll
        for (int w = 0; w < 8; w++) { v += rv[w]; r += rr[w]; }
        out[2097152] = r / 2097152.0f;   // recon_loss = mean over 128*128*128
        out[2097153] = v / 8388608.0f;   // vq_loss    = mean over 128*64*32*32
    }
}

// ============================== launcher =====================================
extern "C" void kernel_launch(void* const* d_in, const int* in_sizes, int n_in,
                              void* d_out, int out_size) {
    const float* x   = (const float*)d_in[0];
    const float* w1  = (const float*)d_in[1];
    const float* b1  = (const float*)d_in[2];
    const float* w2  = (const float*)d_in[3];
    const float* b2  = (const float*)d_in[4];
    const float* w3  = (const float*)d_in[5];
    const float* b3  = (const float*)d_in[6];
    const float* cb  = (const float*)d_in[7];
    const float* dw1 = (const float*)d_in[8];
    const float* db1 = (const float*)d_in[9];
    const float* dw2 = (const float*)d_in[10];
    const float* db2 = (const float*)d_in[11];
    const float* dw3 = (const float*)d_in[12];
    const float* db3 = (const float*)d_in[13];
    float* out = (float*)d_out;

    // symbol addresses for the generic 3x3 kernel (not a stream op; capture-safe)
    float *h2p = 0, *zp = 0, *zqp = 0, *d1p = 0;
    cudaGetSymbolAddress((void**)&h2p, g_h2);
    cudaGetSymbolAddress((void**)&zp,  g_z);
    cudaGetSymbolAddress((void**)&zqp, g_zq);
    cudaGetSymbolAddress((void**)&d1p, g_d1);

    k_conv1  <<<dim3(4, 2, 128), 256>>>(x, w1, b1);
    k_conv2  <<<dim3(4, 128),    256>>>(w2, b2);
    k_conv3x3<<<dim3(4, 128),    256>>>(h2p, w3, b3, zp, 0, 0);   // conv3 -> z
    k_quant  <<<4096,            256>>>(cb);
    k_gather <<<32768,           256>>>(cb);
    k_conv3x3<<<dim3(4, 128),    256>>>(zqp, dw1, db1, d1p, 1, 1); // deconv1
    k_deconv2<<<dim3(2, 4, 128), 256>>>(dw2, db2);
    k_deconv3<<<dim3(4, 128),    256>>>(x, dw3, db3, out);
    k_final  <<<1,               256>>>(out);
}

// round 8
// speedup vs baseline: 1.1979x; 1.1979x over previous
#include <cuda_runtime.h>

// ---------------- scratch buffers (device globals: no allocation allowed) ----
__device__ float g_h1[128*32*64*64];   // encoder conv1 out  [128,32,64,64]
__device__ float g_h2[128*64*32*32];   // encoder conv2 out  [128,64,32,32]
__device__ float g_z [128*64*32*32];   // encoder conv3 out  (z)
__device__ float g_zq[128*64*32*32];   // straight-through z_q
__device__ float g_d1[128*64*32*32];   // decoder deconv1 out
__device__ float g_d2[128*32*64*64];   // decoder deconv2 out
__device__ int   g_idx[128*32*32];     // argmin indices per pixel
__device__ float g_vq_part[32768];
__device__ float g_rec_part[512];

// ---------------- packed f32x2 helpers (FFMA2: 2 fp32 FMAs / instruction) ----
__device__ __forceinline__ void ffma2(unsigned long long& d,
                                      unsigned long long a,
                                      unsigned long long b) {
    asm("fma.rn.f32x2 %0, %1, %2, %0;" : "+l"(d) : "l"(a), "l"(b));
}
__device__ __forceinline__ unsigned long long pack2(float lo, float hi) {
    unsigned long long r;
    asm("mov.b64 %0, {%1, %2};" : "=l"(r) : "f"(lo), "f"(hi));
    return r;
}
__device__ __forceinline__ float2 unpack2(unsigned long long v) {
    float2 f;
    asm("mov.b64 {%0, %1}, %2;" : "=f"(f.x), "=f"(f.y) : "l"(v));
    return f;
}
__device__ __forceinline__ unsigned long long lds_pair(const float* p) {
    // p is 8B-aligned shared-memory address holding (lo, hi)
    return *reinterpret_cast<const unsigned long long*>(p);
}

// =================== conv1: 1->32, 4x4, s2, p1, relu =========================
// in [128,1,128,128] -> out [128,32,64,64]  (small layer: plain FFMA)
__global__ void __launch_bounds__(256) k_conv1(const float* __restrict__ x,
                                               const float* __restrict__ w1,
                                               const float* __restrict__ b1) {
    __shared__ float ws[256];
    const int tid = threadIdx.x;
    const int s = blockIdx.x, cog = blockIdx.y, n = blockIdx.z;
    ws[tid] = w1[cog*256 + tid];
    __syncthreads();
    const int y  = s*16 + (tid >> 4);
    const int x0 = (tid & 15) * 4;
    const float* xn = x + n*16384;
    float acc[16][4];
    #pragma unroll
    for (int j = 0; j < 16; j++) {
        float bv = b1[cog*16 + j];
        #pragma unroll
        for (int p = 0; p < 4; p++) acc[j][p] = bv;
    }
    #pragma unroll
    for (int ky = 0; ky < 4; ky++) {
        int iy = 2*y - 1 + ky;
        bool rok = (iy >= 0) && (iy < 128);
        float xv[10];
        #pragma unroll
        for (int c = 0; c < 10; c++) {
            int ix = 2*x0 - 1 + c;
            xv[c] = (rok && ix >= 0 && ix < 128) ? xn[iy*128 + ix] : 0.f;
        }
        #pragma unroll
        for (int j = 0; j < 16; j++) {
            #pragma unroll
            for (int kx = 0; kx < 4; kx++) {
                float w = ws[j*16 + ky*4 + kx];
                #pragma unroll
                for (int p = 0; p < 4; p++)
                    acc[j][p] = fmaf(xv[2*p + kx], w, acc[j][p]);
            }
        }
    }
    #pragma unroll
    for (int j = 0; j < 16; j++) {
        float4 o;
        o.x = fmaxf(acc[j][0], 0.f); o.y = fmaxf(acc[j][1], 0.f);
        o.z = fmaxf(acc[j][2], 0.f); o.w = fmaxf(acc[j][3], 0.f);
        *(float4*)&g_h1[(n*32 + cog*16 + j)*4096 + y*64 + x0] = o;
    }
}

// =================== conv2: 32->64, 4x4, s2, p1, relu (FFMA2) ================
// in [128,32,64,64] -> out [128,64,32,32]
// smem weights [ci][tap][j] (j fastest) so (j,j+1) pair is one LDS.64
__global__ void __launch_bounds__(256) k_conv2(const float* __restrict__ w2,
                                               const float* __restrict__ b2) {
    __shared__ float ws[32*256];   // [ci][16 taps][16 j]
    const int tid = threadIdx.x;
    const int cog = blockIdx.x, n = blockIdx.y;
    for (int i = tid; i < 8192; i += 256) {
        int ci = i >> 8, r = i & 255, t = r >> 4, j = r & 15;
        ws[i] = w2[(cog*16 + j)*512 + ci*16 + t];
    }
    __syncthreads();
    const int y  = tid >> 3;
    const int x0 = (tid & 7) * 4;
    unsigned long long acc2[8][4];
    #pragma unroll
    for (int j2 = 0; j2 < 8; j2++) {
        unsigned long long bv = pack2(b2[cog*16 + j2*2], b2[cog*16 + j2*2 + 1]);
        #pragma unroll
        for (int p = 0; p < 4; p++) acc2[j2][p] = bv;
    }
    const float* inp = g_h1 + n*131072;
    for (int ci = 0; ci < 32; ci++) {
        const float* ic = inp + ci*4096;
        const float* wc = ws + ci*256;
        #pragma unroll
        for (int ky = 0; ky < 4; ky++) {
            int iy = 2*y - 1 + ky;
            bool rok = (iy >= 0) && (iy < 64);
            unsigned long long xd[10];
            #pragma unroll
            for (int c = 0; c < 10; c++) {
                int ix = 2*x0 - 1 + c;
                float v = (rok && ix >= 0 && ix < 64) ? ic[iy*64 + ix] : 0.f;
                xd[c] = pack2(v, v);
            }
            #pragma unroll
            for (int kx = 0; kx < 4; kx++) {
                #pragma unroll
                for (int j2 = 0; j2 < 8; j2++) {
                    unsigned long long w = lds_pair(wc + (ky*4 + kx)*16 + j2*2);
                    #pragma unroll
                    for (int p = 0; p < 4; p++)
                        ffma2(acc2[j2][p], xd[2*p + kx], w);
                }
            }
        }
    }
    #pragma unroll
    for (int j2 = 0; j2 < 8; j2++) {
        float2 f0 = unpack2(acc2[j2][0]), f1 = unpack2(acc2[j2][1]);
        float2 f2 = unpack2(acc2[j2][2]), f3 = unpack2(acc2[j2][3]);
        float4 lo, hi;
        lo.x = fmaxf(f0.x,0.f); lo.y = fmaxf(f1.x,0.f);
        lo.z = fmaxf(f2.x,0.f); lo.w = fmaxf(f3.x,0.f);
        hi.x = fmaxf(f0.y,0.f); hi.y = fmaxf(f1.y,0.f);
        hi.z = fmaxf(f2.y,0.f); hi.w = fmaxf(f3.y,0.f);
        *(float4*)&g_h2[(n*64 + cog*16 + j2*2    )*1024 + y*32 + x0] = lo;
        *(float4*)&g_h2[(n*64 + cog*16 + j2*2 + 1)*1024 + y*32 + x0] = hi;
    }
}

// ============ generic 64->64 3x3 s1 p1 conv on 32x32 (conv3 / deconv1) ======
// FFMA2 over output-channel pairs. smem weights [ci][tap][j] (j fastest).
__global__ void __launch_bounds__(256) k_conv3x3(const float* __restrict__ in,
                                                 const float* __restrict__ w,
                                                 const float* __restrict__ b,
                                                 float* __restrict__ out,
                                                 int transposed, int do_relu) {
    __shared__ float ws[64*144];   // [ci][9 taps][16 j]
    const int tid = threadIdx.x;
    const int cog = blockIdx.x, n = blockIdx.y;
    for (int i = tid; i < 9216; i += 256) {
        int ci = i / 144, r = i % 144, t = r / 16, j = r & 15;
        int co = cog*16 + j;
        ws[i] = transposed ? w[ci*576 + co*9 + (8 - t)]
                           : w[co*576 + ci*9 + t];
    }
    __syncthreads();
    const int y  = tid >> 3;
    const int x0 = (tid & 7) * 4;
    unsigned long long acc2[8][4];
    #pragma unroll
    for (int j2 = 0; j2 < 8; j2++) {
        unsigned long long bv = pack2(b[cog*16 + j2*2], b[cog*16 + j2*2 + 1]);
        #pragma unroll
        for (int p = 0; p < 4; p++) acc2[j2][p] = bv;
    }
    const float* inp = in + n*65536;
    for (int ci = 0; ci < 64; ci++) {
        const float* ic = inp + ci*1024;
        const float* wc = ws + ci*144;
        #pragma unroll
        for (int ky = 0; ky < 3; ky++) {
            int iy = y - 1 + ky;
            bool rok = (iy >= 0) && (iy < 32);
            unsigned long long xd[6];
            #pragma unroll
            for (int c = 0; c < 6; c++) {
                int ix = x0 - 1 + c;
                float v = (rok && ix >= 0 && ix < 32) ? ic[iy*32 + ix] : 0.f;
                xd[c] = pack2(v, v);
            }
            #pragma unroll
            for (int kx = 0; kx < 3; kx++) {
                #pragma unroll
                for (int j2 = 0; j2 < 8; j2++) {
                    unsigned long long wv = lds_pair(wc + (ky*3 + kx)*16 + j2*2);
                    #pragma unroll
                    for (int p = 0; p < 4; p++)
                        ffma2(acc2[j2][p], xd[p + kx], wv);
                }
            }
        }
    }
    #pragma unroll
    for (int j2 = 0; j2 < 8; j2++) {
        float2 f0 = unpack2(acc2[j2][0]), f1 = unpack2(acc2[j2][1]);
        float2 f2 = unpack2(acc2[j2][2]), f3 = unpack2(acc2[j2][3]);
        float4 lo, hi;
        if (do_relu) {
            lo.x = fmaxf(f0.x,0.f); lo.y = fmaxf(f1.x,0.f);
            lo.z = fmaxf(f2.x,0.f); lo.w = fmaxf(f3.x,0.f);
            hi.x = fmaxf(f0.y,0.f); hi.y = fmaxf(f1.y,0.f);
            hi.z = fmaxf(f2.y,0.f); hi.w = fmaxf(f3.y,0.f);
        } else {
            lo.x = f0.x; lo.y = f1.x; lo.z = f2.x; lo.w = f3.x;
            hi.x = f0.y; hi.y = f1.y; hi.z = f2.y; hi.w = f3.y;
        }
        *(float4*)&out[(n*64 + cog*16 + j2*2    )*1024 + y*32 + x0] = lo;
        *(float4*)&out[(n*64 + cog*16 + j2*2 + 1)*1024 + y*32 + x0] = hi;
    }
}

// =================== VQ argmin: 131072 px, 128 codes, D=64 ===================
__global__ void __launch_bounds__(256) k_quant(const float* __restrict__ cb) {
    __shared__ float4 zs4[64*8];        // [k][px/4] transposed z tile
    __shared__ float  cbs[64*129];      // [k][e] padded
    const int tid = threadIdx.x;
    const int px0 = blockIdx.x * 32;
    const int n = px0 >> 10, hw0 = px0 & 1023;
    const float* zb = g_z + n*65536 + hw0;
    float* zsf = (float*)zs4;
    for (int i = tid; i < 2048; i += 256) {
        int k = i >> 5, px = i & 31;
        zsf[i] = zb[k*1024 + px];
    }
    for (int i = tid; i < 8192; i += 256) {
        int e = i >> 6, k = i & 63;
        cbs[k*129 + e] = cb[i];
    }
    __syncthreads();
    const int cg = tid & 31, pg = tid >> 5;
    float dot[4][4];
    float cc[4];
    #pragma unroll
    for (int j = 0; j < 4; j++) {
        cc[j] = 0.f;
        #pragma unroll
        for (int p = 0; p < 4; p++) dot[j][p] = 0.f;
    }
    for (int k = 0; k < 64; k++) {
        float4 zv = zs4[k*8 + pg];
        #pragma unroll
        for (int j = 0; j < 4; j++) {
            float c = cbs[k*129 + j*32 + cg];
            cc[j] = fmaf(c, c, cc[j]);
            dot[j][0] = fmaf(c, zv.x, dot[j][0]);
            dot[j][1] = fmaf(c, zv.y, dot[j][1]);
            dot[j][2] = fmaf(c, zv.z, dot[j][2]);
            dot[j][3] = fmaf(c, zv.w, dot[j][3]);
        }
    }
    #pragma unroll
    for (int p = 0; p < 4; p++) {
        float bv = cc[0] - 2.f*dot[0][p];
        int   be = cg;
        #pragma unroll
        for (int j = 1; j < 4; j++) {
            float v = cc[j] - 2.f*dot[j][p];
            int   e = j*32 + cg;
            if (v < bv || (v == bv && e < be)) { bv = v; be = e; }
        }
        #pragma unroll
        for (int off = 16; off; off >>= 1) {
            float ov = __shfl_down_sync(0xffffffffu, bv, off);
            int   oe = __shfl_down_sync(0xffffffffu, be, off);
            if (ov < bv || (ov == bv && oe < be)) { bv = ov; be = oe; }
        }
        if (cg == 0) g_idx[px0 + pg*4 + p] = be;
    }
}

// ============== gather z_q + straight-through + vq-loss partials =============
__global__ void __launch_bounds__(256) k_gather(const float* __restrict__ cb) {
    const int i = blockIdx.x*256 + threadIdx.x;
    const int hw = i & 1023;
    const int nc = i >> 10;
    const int c = nc & 63, n = nc >> 6;
    int e = g_idx[n*1024 + hw];
    float zi = g_z[i];
    float v  = __ldg(&cb[e*64 + c]);
    g_zq[i] = zi + (v - zi);
    float d = zi - v;
    float sq = d * d;
    #pragma unroll
    for (int off = 16; off; off >>= 1) sq += __shfl_down_sync(0xffffffffu, sq, off);
    __shared__ float red[8];
    int lane = threadIdx.x & 31, wid = threadIdx.x >> 5;
    if (lane == 0) red[wid] = sq;
    __syncthreads();
    if (threadIdx.x == 0) {
        float s = 0.f;
        #pragma unroll
        for (int w = 0; w < 8; w++) s += red[w];
        g_vq_part[blockIdx.x] = s;
    }
}

// ===== deconv2: ConvTranspose 64->32, 4x4, s2, p1, relu (FFMA2, gather) ======
// in [128,64,32,32] -> out [128,32,64,64]
// smem weights [ci][tap][o] (o fastest) so (o,o+1) pair is one LDS.64
__global__ void __launch_bounds__(256) k_deconv2(const float* __restrict__ dw2,
                                                 const float* __restrict__ db2) {
    __shared__ float ws[64*128];   // [ci][16 taps][8 o]
    const int tid = threadIdx.x;
    const int s = blockIdx.x, og = blockIdx.y, n = blockIdx.z;
    for (int i = tid; i < 8192; i += 256) {
        int ci = i >> 7, r = i & 127, t = r >> 3, o = r & 7;
        ws[i] = dw2[ci*512 + (og*8 + o)*16 + t];
    }
    __syncthreads();
    const int y  = s*32 + (tid >> 3);
    const int x0 = (tid & 7) * 8;
    unsigned long long acc2[4][8];
    #pragma unroll
    for (int j2 = 0; j2 < 4; j2++) {
        unsigned long long bv = pack2(db2[og*8 + j2*2], db2[og*8 + j2*2 + 1]);
        #pragma unroll
        for (int p = 0; p < 8; p++) acc2[j2][p] = bv;
    }
    const int pr  = (y + 1) & 1;
    const int iy1 = (y + 1 - pr) >> 1;
    const int iy2 = iy1 - 1;
    const bool r1ok = (iy1 >= 0) && (iy1 < 32);
    const bool r2ok = (iy2 >= 0) && (iy2 < 32);
    const int ixmin = (x0 - 2) >> 1;
    const float* inp = g_d1 + n*65536;
    for (int ci = 0; ci < 64; ci++) {
        const float* ic = inp + ci*1024;
        const float* wc = ws + ci*128;
        unsigned long long xd0[6], xd1[6];
        #pragma unroll
        for (int c = 0; c < 6; c++) {
            int ix = ixmin + c;
            bool cok = (ix >= 0) && (ix < 32);
            float v0 = (r1ok && cok) ? ic[iy1*32 + ix] : 0.f;
            float v1 = (r2ok && cok) ? ic[iy2*32 + ix] : 0.f;
            xd0[c] = pack2(v0, v0);
            xd1[c] = pack2(v1, v1);
        }
        #pragma unroll
        for (int kxa = 0; kxa < 2; kxa++) {
            // pixels with (p+1)&1 == kxa: kxa=1 -> p even (ca base 1), kxa=0 -> p odd (ca base 2)
            const int cab = kxa ? 1 : 2;
            // ---- row iy1 (ky = pr) ----
            {
                unsigned long long wa[4], wb[4];
                #pragma unroll
                for (int j2 = 0; j2 < 4; j2++) {
                    wa[j2] = lds_pair(wc + (pr*4 + kxa    )*8 + j2*2);
                    wb[j2] = lds_pair(wc + (pr*4 + kxa + 2)*8 + j2*2);
                }
                #pragma unroll
                for (int i4 = 0; i4 < 4; i4++) {
                    int p  = kxa ? (i4*2) : (i4*2 + 1);
                    int ca = cab + i4;
                    #pragma unroll
                    for (int j2 = 0; j2 < 4; j2++) {
                        ffma2(acc2[j2][p], xd0[ca],     wa[j2]);
                        ffma2(acc2[j2][p], xd0[ca - 1], wb[j2]);
                    }
                }
            }
            // ---- row iy2 (ky = pr+2) ----
            {
                unsigned long long wa[4], wb[4];
                #pragma unroll
                for (int j2 = 0; j2 < 4; j2++) {
                    wa[j2] = lds_pair(wc + ((pr+2)*4 + kxa    )*8 + j2*2);
                    wb[j2] = lds_pair(wc + ((pr+2)*4 + kxa + 2)*8 + j2*2);
                }
                #pragma unroll
                for (int i4 = 0; i4 < 4; i4++) {
                    int p  = kxa ? (i4*2) : (i4*2 + 1);
                    int ca = cab + i4;
                    #pragma unroll
                    for (int j2 = 0; j2 < 4; j2++) {
                        ffma2(acc2[j2][p], xd1[ca],     wa[j2]);
                        ffma2(acc2[j2][p], xd1[ca - 1], wb[j2]);
                    }
                }
            }
        }
    }
    #pragma unroll
    for (int j2 = 0; j2 < 4; j2++) {
        float lo[8], hi[8];
        #pragma unroll
        for (int p = 0; p < 8; p++) {
            float2 f = unpack2(acc2[j2][p]);
            lo[p] = fmaxf(f.x, 0.f);
            hi[p] = fmaxf(f.y, 0.f);
        }
        float* opl = &g_d2[(n*32 + og*8 + j2*2    )*4096 + y*64 + x0];
        float* oph = &g_d2[(n*32 + og*8 + j2*2 + 1)*4096 + y*64 + x0];
        *(float4*)opl       = make_float4(lo[0], lo[1], lo[2], lo[3]);
        *(float4*)(opl + 4) = make_float4(lo[4], lo[5], lo[6], lo[7]);
        *(float4*)oph       = make_float4(hi[0], hi[1], hi[2], hi[3]);
        *(float4*)(oph + 4) = make_float4(hi[4], hi[5], hi[6], hi[7]);
    }
}

// ===== deconv3: ConvTranspose 32->1, 4x4, s2, p1, sigmoid + recon loss =======
// FFMA2 over same-parity pixel pairs (p, p+2): input pairs are contiguous xv.
__global__ void __launch_bounds__(256) k_deconv3(const float* __restrict__ x,
                                                 const float* __restrict__ dw3,
                                                 const float* __restrict__ db3,
                                                 float* __restrict__ out) {
    __shared__ float ws[512];      // dw3[32][1][4][4]
    const int tid = threadIdx.x;
    const int s = blockIdx.x, n = blockIdx.y;
    for (int i = tid; i < 512; i += 256) ws[i] = dw3[i];
    __syncthreads();
    const int y  = s*32 + (tid >> 3);
    const int x0 = (tid & 7) * 16;
    unsigned long long acc2[8];    // q = g*4+m: pixels (m*4+g, m*4+g+2)
    {
        float bv = db3[0];
        unsigned long long bp = pack2(bv, bv);
        #pragma unroll
        for (int q = 0; q < 8; q++) acc2[q] = bp;
    }
    const int pr  = (y + 1) & 1;
    const int iy1 = (y + 1 - pr) >> 1;
    const int iy2 = iy1 - 1;
    const bool r1ok = (iy1 >= 0) && (iy1 < 64);
    const bool r2ok = (iy2 >= 0) && (iy2 < 64);
    const int ixmin = (x0 - 2) >> 1;
    const float* inp = g_d2 + n*131072;
    for (int ci = 0; ci < 32; ci++) {
        const float* ic = inp + ci*4096;
        const float* wc = ws + ci*16;
        float xv0[10], xv1[10];
        #pragma unroll
        for (int c = 0; c < 10; c++) {
            int ix = ixmin + c;
            bool cok = (ix >= 0) && (ix < 64);
            xv0[c] = (r1ok && cok) ? ic[iy1*64 + ix] : 0.f;
            xv1[c] = (r2ok && cok) ? ic[iy2*64 + ix] : 0.f;
        }
        unsigned long long xp0[9], xp1[9];
        #pragma unroll
        for (int c = 0; c < 9; c++) {
            xp0[c] = pack2(xv0[c], xv0[c + 1]);
            xp1[c] = pack2(xv1[c], xv1[c + 1]);
        }
        #pragma unroll
        for (int g = 0; g < 2; g++) {
            // g=0: p even -> kxa=1, ca=2m+1 ; g=1: p odd -> kxa=0, ca=2m+2
            const int kxa = g ? 0 : 1;
            float wa1 = wc[pr*4 + kxa],       wb1 = wc[pr*4 + kxa + 2];
            float wa2 = wc[(pr+2)*4 + kxa],   wb2 = wc[(pr+2)*4 + kxa + 2];
            unsigned long long wa1d = pack2(wa1, wa1), wb1d = pack2(wb1, wb1);
            unsigned long long wa2d = pack2(wa2, wa2), wb2d = pack2(wb2, wb2);
            #pragma unroll
            for (int m = 0; m < 4; m++) {
                int ca = 2*m + 1 + g;
                unsigned long long a = acc2[g*4 + m];
                ffma2(a, xp0[ca],     wa1d);
                ffma2(a, xp0[ca - 1], wb1d);
                ffma2(a, xp1[ca],     wa2d);
                ffma2(a, xp1[ca - 1], wb2d);
                acc2[g*4 + m] = a;
            }
        }
    }
    float acc[16];
    #pragma unroll
    for (int g = 0; g < 2; g++)
        #pragma unroll
        for (int m = 0; m < 4; m++) {
            float2 f = unpack2(acc2[g*4 + m]);
            acc[m*4 + g]     = f.x;
            acc[m*4 + g + 2] = f.y;
        }
    // sigmoid, write, accumulate recon-loss partial
    float ssum = 0.f;
    const int obase = n*16384 + y*128 + x0;
    #pragma unroll
    for (int p = 0; p < 16; p++) {
        float v = 1.f / (1.f + __expf(-acc[p]));
        out[obase + p] = v;
        float d = v - x[obase + p];
        ssum = fmaf(d, d, ssum);
    }
    #pragma unroll
    for (int off = 16; off; off >>= 1) ssum += __shfl_down_sync(0xffffffffu, ssum, off);
    __shared__ float red[8];
    int lane = tid & 31, wid = tid >> 5;
    if (lane == 0) red[wid] = ssum;
    __syncthreads();
    if (tid == 0) {
        float sacc = 0.f;
        #pragma unroll
        for (int w = 0; w < 8; w++) sacc += red[w];
        g_rec_part[n*4 + s] = sacc;
    }
}

// =================== final: reduce loss partials -> 2 scalars ================
__global__ void __launch_bounds__(256) k_final(float* __restrict__ out) {
    const int tid = threadIdx.x;
    float vs = 0.f, rs = 0.f;
    for (int i = tid; i < 32768; i += 256) vs += g_vq_part[i];
    for (int i = tid; i < 512;   i += 256) rs += g_rec_part[i];
    #pragma unroll
    for (int off = 16; off; off >>= 1) {
        vs += __shfl_down_sync(0xffffffffu, vs, off);
        rs += __shfl_down_sync(0xffffffffu, rs, off);
    }
    __shared__ float rv[8], rr[8];
    int lane = tid & 31, wid = tid >> 5;
    if (lane == 0) { rv[wid] = vs; rr[wid] = rs; }
    __syncthreads();
    if (tid == 0) {
        float v = 0.f, r = 0.f;
        #pragma unroll
        for (int w = 0; w < 8; w++) { v += rv[w]; r += rr[w]; }
        out[2097152] = r / 2097152.0f;   // recon_loss = mean over 128*128*128
        out[2097153] = v / 8388608.0f;   // vq_loss    = mean over 128*64*32*32
    }
}

// ============================== launcher =====================================
extern "C" void kernel_launch(void* const* d_in, const int* in_sizes, int n_in,
                              void* d_out, int out_size) {
    const float* x   = (const float*)d_in[0];
    const float* w1  = (const float*)d_in[1];
    const float* b1  = (const float*)d_in[2];
    const float* w2  = (const float*)d_in[3];
    const float* b2  = (const float*)d_in[4];
    const float* w3  = (const float*)d_in[5];
    const float* b3  = (const float*)d_in[6];
    const float* cb  = (const float*)d_in[7];
    const float* dw1 = (const float*)d_in[8];
    const float* db1 = (const float*)d_in[9];
    const float* dw2 = (const float*)d_in[10];
    const float* db2 = (const float*)d_in[11];
    const float* dw3 = (const float*)d_in[12];
    const float* db3 = (const float*)d_in[13];
    float* out = (float*)d_out;

    float *h2p = 0, *zp = 0, *zqp = 0, *d1p = 0;
    cudaGetSymbolAddress((void**)&h2p, g_h2);
    cudaGetSymbolAddress((void**)&zp,  g_z);
    cudaGetSymbolAddress((void**)&zqp, g_zq);
    cudaGetSymbolAddress((void**)&d1p, g_d1);

    k_conv1  <<<dim3(4, 2, 128), 256>>>(x, w1, b1);
    k_conv2  <<<dim3(4, 128),    256>>>(w2, b2);
    k_conv3x3<<<dim3(4, 128),    256>>>(h2p, w3, b3, zp, 0, 0);   // conv3 -> z
    k_quant  <<<4096,            256>>>(cb);
    k_gather <<<32768,           256>>>(cb);
    k_conv3x3<<<dim3(4, 128),    256>>>(zqp, dw1, db1, d1p, 1, 1); // deconv1
    k_deconv2<<<dim3(2, 4, 128), 256>>>(dw2, db2);
    k_deconv3<<<dim3(4, 128),    256>>>(x, dw3, db3, out);
    k_final  <<<1,               256>>>(out);
}